// round 14
// baseline (speedup 1.0000x reference)
#include <cuda_runtime.h>

#define VIEWS 512
#define DETS  512
#define H_IMG 256
#define W_IMG 256

// ---- constants (computed in double, used as float) ----
static constexpr double dPI     = 3.14159265358979323846;
static constexpr double dS2R    = 5.95;
static constexpr double dD2R    = 4.906;
static constexpr double dD_DET  = 0.0072;
static constexpr double dVIRDET = dD_DET * dS2R / (dS2R + dD2R);
static constexpr double dD_IMG  = 0.006641;
static constexpr double dD_ANG  = 2.0 * dPI / (double)VIEWS;

// packed f32x2 helpers
__device__ __forceinline__ unsigned long long fma2(unsigned long long a,
                                                   unsigned long long b,
                                                   unsigned long long c) {
    unsigned long long d;
    asm("fma.rn.f32x2 %0, %1, %2, %3;" : "=l"(d) : "l"(a), "l"(b), "l"(c));
    return d;
}

__device__ __forceinline__ unsigned long long add2(unsigned long long a,
                                                   unsigned long long b) {
    unsigned long long d;
    asm("add.rn.f32x2 %0, %1, %2;" : "=l"(d) : "l"(a), "l"(b));
    return d;
}

__device__ __forceinline__ float2 unpack2(unsigned long long v) {
    float2 r;
    asm("mov.b64 {%0, %1}, %2;" : "=f"(r.x), "=f"(r.y) : "l"(v));
    return r;
}

// XOR bank-quad swizzle for the float4 gather table. BIJECTIVE on [0,1024)
// (unlike an additive skew). Spreads stride-2/4/8 lane patterns across all
// 8 bank-quads; stride-4 was a 4-way conflict unswizzled.
__device__ __forceinline__ int skew(int k) { return k ^ ((k >> 3) & 7); }

// ============================================================================
// Fused per-VIEW kernel. Grid: 512 blocks (one per view v), 512 threads.
// One launch, no global scratch, no duplicated filter work.
//
// Phase 1 (filter): ramp filter nonzero only at center tap + odd offsets
// (even filt indices). Ge[n] = filt[2n]; tap quad Gq[n] =
// (Ge[n-1],Ge[n],Ge[n],Ge[n+1]) is 16B-aligned at every n -> one LDS.128
// yields packed (O,E) tap pairs for two s-iterations; q rows are LDS.128
// broadcasts. Thread (jt = tid&127, sq = tid>>7): 2 rows (b0,b1) x 2
// a-values (jt, jt+128), s-QUARTER sq. Partial sums combined via packed
// f32x2 tree reduction through the dead tap-table region.
//
// Phase 2 tables: frB[col] = (b0, b1), zero-padded to 1024 cols (bias
// +383.5) -> no validity masks; then fr4[skew(k)] =
// (b0[k],b1[k],b0[k+1],b1[k+1]) so each pixel's bilinear gather is ONE
// aligned LDS.128 on a conflict-swizzled layout.
//
// Phase 2 (backproject): all 256x256 pixels of view v. 128 x-pairs x 4 ty,
// 64 iters. Per iter: 2 geometries, 2 LDS.128 gathers, 4 outputs, 2 STG.64.
// ============================================================================
__global__ __launch_bounds__(512, 3)
void fbp_kernel(const float* __restrict__ proj,
                const float* __restrict__ w,
                const float* __restrict__ filt,
                float* __restrict__ out) {
    __shared__ __align__(16) union {
        struct {
            float  q[2][DETS];     // 4 KB  [b][c]
            float4 Gq[DETS];       // 8 KB  (later: reduction buffer)
        } p1;
        struct {
            float2 frB[1024];      // 8 KB  (overlays q + low half of Gq)
            float4 fr4[1024];      // 16 KB (XOR-swizzled)
        } p2;
    } sm;

    const int tid = threadIdx.x;
    const int v   = blockIdx.x;          // view

    // ---- load tap table + weighted sinogram rows (b0, b1 of view v) ----
    for (int n = tid; n < DETS; n += 512) {
        float gm = (n >= 1)   ? filt[2 * n - 2] : 0.0f;   // Ge[n-1]
        float ge = filt[2 * n];                            // Ge[n]
        float gp = (n <= 510) ? filt[2 * n + 2] : 0.0f;   // Ge[n+1]
        sm.p1.Gq[n] = make_float4(gm, ge, ge, gp);
    }
    for (int idx = tid; idx < 2 * DETS; idx += 512) {
        const int b = idx >> 9;
        const int c = idx & (DETS - 1);
        sm.p1.q[b][c] = proj[(b * VIEWS + v) * DETS + c] * w[c];
    }
    __syncthreads();

    // ---- Phase 1: ramp filter, s-quartered ----
    const int jt = tid & 127;
    const int sq = tid >> 7;             // s-quarter [0,4)

    unsigned long long acc[2][2];        // [row b][a], packed (O, E)
    acc[0][0] = acc[0][1] = acc[1][0] = acc[1][1] = 0ull;
    {
        const int gi0 = 256 - jt;        // iter n = gi0 + s  (a0 = jt)
        const int gi1 = 128 - jt;        // iter n = gi1 + s  (a1 = jt + 128)
        const int sp0 = sq * 32;

#pragma unroll 2
        for (int spp = 0; spp < 32; ++spp) {
            const int sp = sp0 + spp;
            const ulonglong2 g0 = *(const ulonglong2*)&sm.p1.Gq[gi0 + 2 * sp];
            const ulonglong2 g1 = *(const ulonglong2*)&sm.p1.Gq[gi1 + 2 * sp];
            const ulonglong2 q0 = *(const ulonglong2*)&sm.p1.q[0][4 * sp];
            const ulonglong2 q1 = *(const ulonglong2*)&sm.p1.q[1][4 * sp];

            acc[0][0] = fma2(q0.x, g0.x, acc[0][0]);
            acc[0][0] = fma2(q0.y, g0.y, acc[0][0]);
            acc[0][1] = fma2(q0.x, g1.x, acc[0][1]);
            acc[0][1] = fma2(q0.y, g1.y, acc[0][1]);
            acc[1][0] = fma2(q1.x, g0.x, acc[1][0]);
            acc[1][0] = fma2(q1.y, g0.y, acc[1][0]);
            acc[1][1] = fma2(q1.x, g1.x, acc[1][1]);
            acc[1][1] = fma2(q1.y, g1.y, acc[1][1]);
        }
    }
    __syncthreads();   // Gq reads done; its 8 KB becomes the reduction buffer

    unsigned long long* buf = (unsigned long long*)sm.p1.Gq;  // 1024 ull
    // round 1: quarters 1,3 publish; 0,2 absorb
    if (sq & 1) {
        ulonglong2* r = (ulonglong2*)(buf + ((sq >> 1) * 128 + jt) * 4);
        r[0] = make_ulonglong2(acc[0][0], acc[0][1]);
        r[1] = make_ulonglong2(acc[1][0], acc[1][1]);
    }
    __syncthreads();
    if (!(sq & 1)) {
        const ulonglong2* r = (const ulonglong2*)(buf + ((sq >> 1) * 128 + jt) * 4);
        const ulonglong2 r0 = r[0];
        const ulonglong2 r1 = r[1];
        acc[0][0] = add2(acc[0][0], r0.x);
        acc[0][1] = add2(acc[0][1], r0.y);
        acc[1][0] = add2(acc[1][0], r1.x);
        acc[1][1] = add2(acc[1][1], r1.y);
    }
    __syncthreads();
    // round 2: quarter 2 publishes; 0 absorbs
    if (sq == 2) {
        ulonglong2* r = (ulonglong2*)(buf + jt * 4);
        r[0] = make_ulonglong2(acc[0][0], acc[0][1]);
        r[1] = make_ulonglong2(acc[1][0], acc[1][1]);
    }
    __syncthreads();

    float e0b0, o0b0, e1b0, o1b0, e0b1, o0b1, e1b1, o1b1;
    if (sq == 0) {
        const ulonglong2* r = (const ulonglong2*)(buf + jt * 4);
        const ulonglong2 r0 = r[0];
        const ulonglong2 r1 = r[1];
        acc[0][0] = add2(acc[0][0], r0.x);
        acc[0][1] = add2(acc[0][1], r0.y);
        acc[1][0] = add2(acc[1][0], r1.x);
        acc[1][1] = add2(acc[1][1], r1.y);

        const float fc = filt[511];      // center tap
        const int j0 = 2 * jt;
        const int j1 = 2 * jt + 256;

        const float2 oe00 = unpack2(acc[0][0]);   // b0, j0: (O, E)
        const float2 oe01 = unpack2(acc[0][1]);   // b0, j1
        const float2 oe10 = unpack2(acc[1][0]);   // b1, j0
        const float2 oe11 = unpack2(acc[1][1]);   // b1, j1

        e0b0 = fmaf(fc, sm.p1.q[0][j0],     oe00.y);
        o0b0 = fmaf(fc, sm.p1.q[0][j0 + 1], oe00.x);
        e1b0 = fmaf(fc, sm.p1.q[0][j1],     oe01.y);
        o1b0 = fmaf(fc, sm.p1.q[0][j1 + 1], oe01.x);
        e0b1 = fmaf(fc, sm.p1.q[1][j0],     oe10.y);
        o0b1 = fmaf(fc, sm.p1.q[1][j0 + 1], oe10.x);
        e1b1 = fmaf(fc, sm.p1.q[1][j1],     oe11.y);
        o1b1 = fmaf(fc, sm.p1.q[1][j1 + 1], oe11.x);
    }

    const float beta = (float)dD_ANG * (float)v;
    float sb, cb;
    sincosf(beta, &sb, &cb);
    __syncthreads();   // phase-1 smem fully consumed; overlay becomes frB

    // ---- build frB (data + zero pads) ----
    if (sq == 0) {
        const int j0 = 2 * jt;
        const int j1 = 2 * jt + 256;
        sm.p2.frB[128 + j0]     = make_float2(e0b0, e0b1);
        sm.p2.frB[128 + j0 + 1] = make_float2(o0b0, o0b1);
        sm.p2.frB[128 + j1]     = make_float2(e1b0, e1b1);
        sm.p2.frB[128 + j1 + 1] = make_float2(o1b0, o1b1);
    }
    {   // zero cols [0,128) and [640,1024): 512 cols, one per thread
        const int col = (tid < 128) ? tid : (tid + 512);
        sm.p2.frB[col] = make_float2(0.0f, 0.0f);
    }
    __syncthreads();

    // ---- build fr4[skew(k)] = (b0[k], b1[k], b0[k+1], b1[k+1]) ----
#pragma unroll
    for (int kk = 0; kk < 2; ++kk) {
        const int k = tid + kk * 512;
        const float2 fa = sm.p2.frB[k];
        const float2 fb = (k < 1023) ? sm.p2.frB[k + 1] : make_float2(0.0f, 0.0f);
        sm.p2.fr4[skew(k)] = make_float4(fa.x, fa.y, fb.x, fb.y);
    }
    __syncthreads();

    // ---- Phase 2: back-projection of view v ----
    const float S2R  = (float)dS2R;
    const float DIMG = (float)dD_IMG;
    const float K    = (float)(dS2R / dVIRDET);
    const float Kcb  = K * cb;

    const int tx = tid & 127;        // x-pair: x0 = 2tx, x1 = 2tx+1
    const int ty = tid >> 7;         // y offset within group of 4 rows

    const float xs0 = (2.0f * (float)tx - 127.5f) * DIMG;
    const float xs1 = xs0 + DIMG;
    const float A0  = S2R - xs0 * cb;      // d = A - ys*sb
    const float A1  = S2R - xs1 * cb;
    const float B0  = K * (xs0 * sb);      // num = ys*Kcb - B
    const float B1  = K * (xs1 * sb);

    const int bstr = VIEWS * H_IMG * W_IMG;
    float* p0 = out + (v * H_IMG + ty) * W_IMG + 2 * tx;

#pragma unroll 4
    for (int i = 0; i < 64; ++i) {
        const float yv    = (float)(4 * i + ty);
        const float ys    = (127.5f - yv) * DIMG;
        const float yssb  = ys * sb;
        const float ysKcb = ys * Kcb;

        const float d0   = A0 - yssb;
        const float d1   = A1 - yssb;
        const float inv0 = __fdividef(1.0f, d0);
        const float inv1 = __fdividef(1.0f, d1);
        const float t0   = fmaf(ysKcb - B0, inv0, 383.5f);   // +255.5 +128 pad
        const float t1   = fmaf(ysKcb - B1, inv1, 383.5f);
        float wg0 = S2R * inv0; wg0 *= wg0;
        float wg1 = S2R * inv1; wg1 *= wg1;

        const float fl0 = floorf(t0);
        const float fl1 = floorf(t1);
        const float h0  = t0 - fl0;
        const float h1  = t1 - fl1;
        const int   j0  = (int)fl0;                          // in [3, 763]
        const int   j1  = (int)fl1;

        // one aligned LDS.128 per pixel on the swizzled table
        const float4 f0 = sm.p2.fr4[skew(j0)];
        const float4 f1 = sm.p2.fr4[skew(j1)];

        const float b0x0 = wg0 * fmaf(h0, f0.z - f0.x, f0.x);
        const float b1x0 = wg0 * fmaf(h0, f0.w - f0.y, f0.y);
        const float b0x1 = wg1 * fmaf(h1, f1.z - f1.x, f1.x);
        const float b1x1 = wg1 * fmaf(h1, f1.w - f1.y, f1.y);

        *(float2*)(p0)        = make_float2(b0x0, b0x1);
        *(float2*)(p0 + bstr) = make_float2(b1x0, b1x1);

        p0 += 4 * W_IMG;
    }
}

extern "C" void kernel_launch(void* const* d_in, const int* in_sizes, int n_in,
                              void* d_out, int out_size) {
    const float* proj = (const float*)d_in[0];   // (2,1,512,512)
    const float* w    = (const float*)d_in[1];   // (1,1,1,512)
    const float* filt = (const float*)d_in[2];   // (1,1,1,1023)
    float* out = (float*)d_out;                  // (2,512,256,256)

    fbp_kernel<<<512, 512>>>(proj, w, filt, out);
}

// round 16
// speedup vs baseline: 1.1453x; 1.1453x over previous
#include <cuda_runtime.h>
#include <cuda_fp16.h>

#define VIEWS 512
#define DETS  512
#define H_IMG 256
#define W_IMG 256

// ---- constants (computed in double, used as float) ----
static constexpr double dPI     = 3.14159265358979323846;
static constexpr double dS2R    = 5.95;
static constexpr double dD2R    = 4.906;
static constexpr double dD_DET  = 0.0072;
static constexpr double dVIRDET = dD_DET * dS2R / (dS2R + dD2R);
static constexpr double dD_IMG  = 0.006641;
static constexpr double dD_ANG  = 2.0 * dPI / (double)VIEWS;

// packed f32x2 helpers
__device__ __forceinline__ unsigned long long fma2(unsigned long long a,
                                                   unsigned long long b,
                                                   unsigned long long c) {
    unsigned long long d;
    asm("fma.rn.f32x2 %0, %1, %2, %3;" : "=l"(d) : "l"(a), "l"(b), "l"(c));
    return d;
}

__device__ __forceinline__ unsigned long long add2(unsigned long long a,
                                                   unsigned long long b) {
    unsigned long long d;
    asm("add.rn.f32x2 %0, %1, %2;" : "=l"(d) : "l"(a), "l"(b));
    return d;
}

__device__ __forceinline__ float2 unpack2(unsigned long long v) {
    float2 r;
    asm("mov.b64 {%0, %1}, %2;" : "=f"(r.x), "=f"(r.y) : "l"(v));
    return r;
}

// bit-casts (the missing __half2_as_uint / __uint_as_half2)
__device__ __forceinline__ unsigned h2_to_u32(__half2 h) {
    return *reinterpret_cast<const unsigned*>(&h);
}
__device__ __forceinline__ __half2 u32_to_h2(unsigned u) {
    return *reinterpret_cast<const __half2*>(&u);
}

// ============================================================================
// Fused per-VIEW kernel. Grid: 512 blocks (one per view v), 512 threads.
// One launch, no global scratch, no duplicated filter work.
//
// Phase 1 (filter, fp32): ramp filter nonzero only at center tap + odd
// offsets (even filt indices). Ge[n] = filt[2n]; tap quad Gq[n] =
// (Ge[n-1],Ge[n],Ge[n],Ge[n+1]) is 16B-aligned at every n -> one LDS.128
// yields packed (O,E) tap pairs for two s-iterations; q rows are LDS.128
// broadcasts. Thread (jt = tid&127, sq = tid>>7): 2 rows (b0,b1) x 2
// a-values (jt, jt+128), s-QUARTER sq. Partial sums combined via packed
// f32x2 tree reduction through the dead tap-table region.
//
// Phase 2 tables: frB[col] = fp32 (b0, b1), zero-padded to 1024 cols (bias
// +383.5) -> no validity masks; then the HALF-PRECISION gather table
// fr4h[k] = ( half2(b0[k],b1[k]), half2(b0[k+1],b1[k+1]) ): each pixel's
// bilinear gather becomes ONE LDS.64 (8 B/lane instead of 16 -> half the
// crossbar wavefronts). Lerp still evaluated in fp32.
//
// Phase 2 (backproject): all 256x256 pixels of view v. 128 x-pairs x 4 ty,
// 64 iters. Per iter: 2 geometries, 2 LDS.64 gathers, 4 outputs, 2 STG.64.
// ============================================================================
__global__ __launch_bounds__(512, 3)
void fbp_kernel(const float* __restrict__ proj,
                const float* __restrict__ w,
                const float* __restrict__ filt,
                float* __restrict__ out) {
    __shared__ __align__(16) union {
        struct {
            float  q[2][DETS];     // 4 KB  [b][c]
            float4 Gq[DETS];       // 8 KB  (later: reduction buffer)
        } p1;
        struct {
            float2 frB[1024];      // 8 KB  (overlays q + low half of Gq)
            uint2  fr4h[1024];     // 8 KB  fp16 gather table
        } p2;
    } sm;

    const int tid = threadIdx.x;
    const int v   = blockIdx.x;          // view

    // ---- load tap table + weighted sinogram rows (b0, b1 of view v) ----
    for (int n = tid; n < DETS; n += 512) {
        float gm = (n >= 1)   ? filt[2 * n - 2] : 0.0f;   // Ge[n-1]
        float ge = filt[2 * n];                            // Ge[n]
        float gp = (n <= 510) ? filt[2 * n + 2] : 0.0f;   // Ge[n+1]
        sm.p1.Gq[n] = make_float4(gm, ge, ge, gp);
    }
    for (int idx = tid; idx < 2 * DETS; idx += 512) {
        const int b = idx >> 9;
        const int c = idx & (DETS - 1);
        sm.p1.q[b][c] = proj[(b * VIEWS + v) * DETS + c] * w[c];
    }
    __syncthreads();

    // ---- Phase 1: ramp filter, s-quartered ----
    const int jt = tid & 127;
    const int sq = tid >> 7;             // s-quarter [0,4)

    unsigned long long acc[2][2];        // [row b][a], packed (O, E)
    acc[0][0] = acc[0][1] = acc[1][0] = acc[1][1] = 0ull;
    {
        const int gi0 = 256 - jt;        // iter n = gi0 + s  (a0 = jt)
        const int gi1 = 128 - jt;        // iter n = gi1 + s  (a1 = jt + 128)
        const int sp0 = sq * 32;

#pragma unroll 2
        for (int spp = 0; spp < 32; ++spp) {
            const int sp = sp0 + spp;
            const ulonglong2 g0 = *(const ulonglong2*)&sm.p1.Gq[gi0 + 2 * sp];
            const ulonglong2 g1 = *(const ulonglong2*)&sm.p1.Gq[gi1 + 2 * sp];
            const ulonglong2 q0 = *(const ulonglong2*)&sm.p1.q[0][4 * sp];
            const ulonglong2 q1 = *(const ulonglong2*)&sm.p1.q[1][4 * sp];

            acc[0][0] = fma2(q0.x, g0.x, acc[0][0]);
            acc[0][0] = fma2(q0.y, g0.y, acc[0][0]);
            acc[0][1] = fma2(q0.x, g1.x, acc[0][1]);
            acc[0][1] = fma2(q0.y, g1.y, acc[0][1]);
            acc[1][0] = fma2(q1.x, g0.x, acc[1][0]);
            acc[1][0] = fma2(q1.y, g0.y, acc[1][0]);
            acc[1][1] = fma2(q1.x, g1.x, acc[1][1]);
            acc[1][1] = fma2(q1.y, g1.y, acc[1][1]);
        }
    }
    __syncthreads();   // Gq reads done; its 8 KB becomes the reduction buffer

    unsigned long long* buf = (unsigned long long*)sm.p1.Gq;  // 1024 ull
    // round 1: quarters 1,3 publish; 0,2 absorb
    if (sq & 1) {
        ulonglong2* r = (ulonglong2*)(buf + ((sq >> 1) * 128 + jt) * 4);
        r[0] = make_ulonglong2(acc[0][0], acc[0][1]);
        r[1] = make_ulonglong2(acc[1][0], acc[1][1]);
    }
    __syncthreads();
    if (!(sq & 1)) {
        const ulonglong2* r = (const ulonglong2*)(buf + ((sq >> 1) * 128 + jt) * 4);
        const ulonglong2 r0 = r[0];
        const ulonglong2 r1 = r[1];
        acc[0][0] = add2(acc[0][0], r0.x);
        acc[0][1] = add2(acc[0][1], r0.y);
        acc[1][0] = add2(acc[1][0], r1.x);
        acc[1][1] = add2(acc[1][1], r1.y);
    }
    __syncthreads();
    // round 2: quarter 2 publishes; 0 absorbs
    if (sq == 2) {
        ulonglong2* r = (ulonglong2*)(buf + jt * 4);
        r[0] = make_ulonglong2(acc[0][0], acc[0][1]);
        r[1] = make_ulonglong2(acc[1][0], acc[1][1]);
    }
    __syncthreads();

    float e0b0, o0b0, e1b0, o1b0, e0b1, o0b1, e1b1, o1b1;
    if (sq == 0) {
        const ulonglong2* r = (const ulonglong2*)(buf + jt * 4);
        const ulonglong2 r0 = r[0];
        const ulonglong2 r1 = r[1];
        acc[0][0] = add2(acc[0][0], r0.x);
        acc[0][1] = add2(acc[0][1], r0.y);
        acc[1][0] = add2(acc[1][0], r1.x);
        acc[1][1] = add2(acc[1][1], r1.y);

        const float fc = filt[511];      // center tap
        const int j0 = 2 * jt;
        const int j1 = 2 * jt + 256;

        const float2 oe00 = unpack2(acc[0][0]);   // b0, j0: (O, E)
        const float2 oe01 = unpack2(acc[0][1]);   // b0, j1
        const float2 oe10 = unpack2(acc[1][0]);   // b1, j0
        const float2 oe11 = unpack2(acc[1][1]);   // b1, j1

        e0b0 = fmaf(fc, sm.p1.q[0][j0],     oe00.y);
        o0b0 = fmaf(fc, sm.p1.q[0][j0 + 1], oe00.x);
        e1b0 = fmaf(fc, sm.p1.q[0][j1],     oe01.y);
        o1b0 = fmaf(fc, sm.p1.q[0][j1 + 1], oe01.x);
        e0b1 = fmaf(fc, sm.p1.q[1][j0],     oe10.y);
        o0b1 = fmaf(fc, sm.p1.q[1][j0 + 1], oe10.x);
        e1b1 = fmaf(fc, sm.p1.q[1][j1],     oe11.y);
        o1b1 = fmaf(fc, sm.p1.q[1][j1 + 1], oe11.x);
    }

    const float beta = (float)dD_ANG * (float)v;
    float sb, cb;
    sincosf(beta, &sb, &cb);
    __syncthreads();   // phase-1 smem fully consumed; overlay becomes frB

    // ---- build frB (data + zero pads) ----
    if (sq == 0) {
        const int j0 = 2 * jt;
        const int j1 = 2 * jt + 256;
        sm.p2.frB[128 + j0]     = make_float2(e0b0, e0b1);
        sm.p2.frB[128 + j0 + 1] = make_float2(o0b0, o0b1);
        sm.p2.frB[128 + j1]     = make_float2(e1b0, e1b1);
        sm.p2.frB[128 + j1 + 1] = make_float2(o1b0, o1b1);
    }
    {   // zero cols [0,128) and [640,1024): 512 cols, one per thread
        const int col = (tid < 128) ? tid : (tid + 512);
        sm.p2.frB[col] = make_float2(0.0f, 0.0f);
    }
    __syncthreads();

    // ---- build fp16 gather table fr4h[k] = (h2(b0,b1)[k], h2(b0,b1)[k+1]) ----
#pragma unroll
    for (int kk = 0; kk < 2; ++kk) {
        const int k = tid + kk * 512;
        const float2 fa = sm.p2.frB[k];
        const float2 fb = (k < 1023) ? sm.p2.frB[k + 1] : make_float2(0.0f, 0.0f);
        const __half2 ha = __float22half2_rn(fa);
        const __half2 hb = __float22half2_rn(fb);
        sm.p2.fr4h[k] = make_uint2(h2_to_u32(ha), h2_to_u32(hb));
    }
    __syncthreads();

    // ---- Phase 2: back-projection of view v ----
    const float S2R  = (float)dS2R;
    const float DIMG = (float)dD_IMG;
    const float K    = (float)(dS2R / dVIRDET);
    const float Kcb  = K * cb;

    const int tx = tid & 127;        // x-pair: x0 = 2tx, x1 = 2tx+1
    const int ty = tid >> 7;         // y offset within group of 4 rows

    const float xs0 = (2.0f * (float)tx - 127.5f) * DIMG;
    const float xs1 = xs0 + DIMG;
    const float A0  = S2R - xs0 * cb;      // d = A - ys*sb
    const float A1  = S2R - xs1 * cb;
    const float B0  = K * (xs0 * sb);      // num = ys*Kcb - B
    const float B1  = K * (xs1 * sb);

    const int bstr = VIEWS * H_IMG * W_IMG;
    float* p0 = out + (v * H_IMG + ty) * W_IMG + 2 * tx;

#pragma unroll 4
    for (int i = 0; i < 64; ++i) {
        const float yv    = (float)(4 * i + ty);
        const float ys    = (127.5f - yv) * DIMG;
        const float yssb  = ys * sb;
        const float ysKcb = ys * Kcb;

        const float d0   = A0 - yssb;
        const float d1   = A1 - yssb;
        const float inv0 = __fdividef(1.0f, d0);
        const float inv1 = __fdividef(1.0f, d1);
        const float t0   = fmaf(ysKcb - B0, inv0, 383.5f);   // +255.5 +128 pad
        const float t1   = fmaf(ysKcb - B1, inv1, 383.5f);
        float wg0 = S2R * inv0; wg0 *= wg0;
        float wg1 = S2R * inv1; wg1 *= wg1;

        const float fl0 = floorf(t0);
        const float fl1 = floorf(t1);
        const float h0  = t0 - fl0;
        const float h1  = t1 - fl1;
        const int   j0  = (int)fl0;                          // in [3, 763]
        const int   j1  = (int)fl1;

        // one LDS.64 per pixel: (h2(b0,b1)[j], h2(b0,b1)[j+1])
        const uint2 g0 = sm.p2.fr4h[j0];
        const uint2 g1 = sm.p2.fr4h[j1];
        const float2 a0 = __half22float2(u32_to_h2(g0.x));
        const float2 c0 = __half22float2(u32_to_h2(g0.y));
        const float2 a1 = __half22float2(u32_to_h2(g1.x));
        const float2 c1 = __half22float2(u32_to_h2(g1.y));

        const float b0x0 = wg0 * fmaf(h0, c0.x - a0.x, a0.x);
        const float b1x0 = wg0 * fmaf(h0, c0.y - a0.y, a0.y);
        const float b0x1 = wg1 * fmaf(h1, c1.x - a1.x, a1.x);
        const float b1x1 = wg1 * fmaf(h1, c1.y - a1.y, a1.y);

        *(float2*)(p0)        = make_float2(b0x0, b0x1);
        *(float2*)(p0 + bstr) = make_float2(b1x0, b1x1);

        p0 += 4 * W_IMG;
    }
}

extern "C" void kernel_launch(void* const* d_in, const int* in_sizes, int n_in,
                              void* d_out, int out_size) {
    const float* proj = (const float*)d_in[0];   // (2,1,512,512)
    const float* w    = (const float*)d_in[1];   // (1,1,1,512)
    const float* filt = (const float*)d_in[2];   // (1,1,1,1023)
    float* out = (float*)d_out;                  // (2,512,256,256)

    fbp_kernel<<<512, 512>>>(proj, w, filt, out);
}